// round 15
// baseline (speedup 1.0000x reference)
#include <cuda_runtime.h>
#include <cuda_bf16.h>
#include <cuda_fp16.h>
#include <cstdint>

#define N_NODES 50000
#define N_EDGES 800000
#define F 128
#define ELL_CAP 64        // P(Poisson(16) >= 64) ~ 4e-18; clamped defensively

// ---------------------------------------------------------------------------
// Device-global scratch (allocation-free rule)
// ---------------------------------------------------------------------------
__device__ __half2 g_supp[(size_t)N_NODES * 64];         // X @ W in fp16 (12.8 MB)
__device__ int     g_cnt[N_NODES];                       // per-row edge count
__device__ int2    g_ell[(size_t)N_NODES * ELL_CAP];     // padded bins {col, val bits} (25.6 MB)
__device__ __nv_bfloat16 g_whi[128 * 128];               // W^T hi, row-major [n][k]
__device__ __nv_bfloat16 g_wlo[128 * 128];               // W^T lo

// ---------------------------------------------------------------------------
// helpers
// ---------------------------------------------------------------------------
__device__ __forceinline__ uint32_t smem_u32(const void* p) {
    uint32_t a;
    asm("{ .reg .u64 t; cvta.to.shared.u64 t, %1; cvt.u32.u64 %0, t; }" : "=r"(a) : "l"(p));
    return a;
}
__device__ __forceinline__ void ldsm_x4(uint32_t* r, uint32_t addr) {
    asm volatile("ldmatrix.sync.aligned.m8n8.x4.shared.b16 {%0,%1,%2,%3}, [%4];"
                 : "=r"(r[0]), "=r"(r[1]), "=r"(r[2]), "=r"(r[3]) : "r"(addr));
}
__device__ __forceinline__ void mma_bf16(float* d, const uint32_t* a, const uint32_t* b) {
    asm volatile("mma.sync.aligned.m16n8k16.row.col.f32.bf16.bf16.f32 "
                 "{%0,%1,%2,%3}, {%4,%5,%6,%7}, {%8,%9}, {%0,%1,%2,%3};"
                 : "+f"(d[0]), "+f"(d[1]), "+f"(d[2]), "+f"(d[3])
                 : "r"(a[0]), "r"(a[1]), "r"(a[2]), "r"(a[3]), "r"(b[0]), "r"(b[1]));
}
__device__ __forceinline__ uint32_t packbf(float a, float b) {
    uint32_t r;
    asm("cvt.rn.bf16x2.f32 %0, %1, %2;" : "=r"(r) : "f"(b), "f"(a));
    return r;
}

// ---------------------------------------------------------------------------
// 1) single-pass edge scatter into padded ELL bins
// ---------------------------------------------------------------------------
__global__ void k_scatter_ell(const int* __restrict__ edge_row,
                              const int* __restrict__ edge_col,
                              const float* __restrict__ edge_val) {
    int t = blockIdx.x * blockDim.x + threadIdx.x;
    int e0 = t * 2;
    if (e0 >= N_EDGES) return;

    int2   r2 = ((const int2*)edge_row)[t];
    int2   c2 = ((const int2*)edge_col)[t];
    float2 v2 = ((const float2*)edge_val)[t];

    int pos0 = atomicAdd(&g_cnt[r2.x], 1);
    if (pos0 < ELL_CAP)
        g_ell[(size_t)r2.x * ELL_CAP + pos0] = make_int2(c2.x, __float_as_int(v2.x));
    int pos1 = atomicAdd(&g_cnt[r2.y], 1);
    if (pos1 < ELL_CAP)
        g_ell[(size_t)r2.y * ELL_CAP + pos1] = make_int2(c2.y, __float_as_int(v2.y));
}

// ---------------------------------------------------------------------------
// 2) prep: W[K][N] -> W^T bf16 hi/lo, row-major [n][k]
// ---------------------------------------------------------------------------
__global__ void k_prep_w(const float* __restrict__ weight) {
    int k = blockIdx.x;     // 128 blocks
    int n = threadIdx.x;    // 128 threads, coalesced read
    float v = weight[k * 128 + n];
    __nv_bfloat16 h = __float2bfloat16(v);
    g_whi[n * 128 + k] = h;
    g_wlo[n * 128 + k] = __float2bfloat16(v - __bfloat162float(h));
}

// ---------------------------------------------------------------------------
// 3) GEMM via mma.sync bf16-split: g_supp = fp16(X @ W)
//    CTA = 128x128, 8 warps tiled 4(m) x 2(n): warp = 32 rows x 64 cols.
// ---------------------------------------------------------------------------
#define STRIDE 136
#define PLANE  (128 * STRIDE)               // bf16 elems per plane
#define MT_BYTES (16 * STRIDE * 2)          // 16 rows, bytes
#define SMEM_GEMM (4 * PLANE * (int)sizeof(__nv_bfloat16))

__global__ void __launch_bounds__(256, 1)
k_gemm_mma(const float* __restrict__ x) {
    extern __shared__ __nv_bfloat16 sm[];
    __nv_bfloat16* sAh = sm;
    __nv_bfloat16* sAl = sm + PLANE;
    __nv_bfloat16* sWh = sm + 2 * PLANE;
    __nv_bfloat16* sWl = sm + 3 * PLANE;

    int tid = threadIdx.x;
    int warp = tid >> 5;
    int lane = tid & 31;
    int row0 = blockIdx.x * 128;

    // stage W planes (row n = 256 B = 16 uint4)
    for (int i = tid; i < 128 * 16; i += 256) {
        int n = i >> 4, q = i & 15;
        ((uint4*)(sWh + n * STRIDE))[q] = ((const uint4*)(g_whi + n * 128))[q];
        ((uint4*)(sWl + n * STRIDE))[q] = ((const uint4*)(g_wlo + n * 128))[q];
    }

    // convert X tile -> bf16 hi/lo. thread t: row = t/2, k-half = t%2
    {
        int row = tid >> 1;
        int kb = (tid & 1) * 64;
        int gr = row0 + row;
        bool valid = (gr < N_NODES);
        const float4* src = (const float4*)(x + (size_t)(valid ? gr : 0) * F + kb);
#pragma unroll
        for (int q = 0; q < 16; q++) {
            float4 v = valid ? src[q] : make_float4(0.f, 0.f, 0.f, 0.f);
            int c = kb + q * 4;
            uint32_t hp0 = packbf(v.x, v.y);
            __nv_bfloat162 h0 = *reinterpret_cast<__nv_bfloat162*>(&hp0);
            uint32_t lp0 = packbf(v.x - __bfloat162float(h0.x), v.y - __bfloat162float(h0.y));
            uint32_t hp1 = packbf(v.z, v.w);
            __nv_bfloat162 h1 = *reinterpret_cast<__nv_bfloat162*>(&hp1);
            uint32_t lp1 = packbf(v.z - __bfloat162float(h1.x), v.w - __bfloat162float(h1.y));
            *(uint32_t*)(sAh + row * STRIDE + c)     = hp0;
            *(uint32_t*)(sAl + row * STRIDE + c)     = lp0;
            *(uint32_t*)(sAh + row * STRIDE + c + 2) = hp1;
            *(uint32_t*)(sAl + row * STRIDE + c + 2) = lp1;
        }
    }
    __syncthreads();

    int warp_m = warp & 3;            // rows warp_m*32
    int warp_n = warp >> 2;           // cols warp_n*64
    int wrow = warp_m * 32;
    int ncol0 = warp_n * 64;

    float d[2][8][4];
#pragma unroll
    for (int mt = 0; mt < 2; mt++)
#pragma unroll
        for (int nt = 0; nt < 8; nt++)
#pragma unroll
            for (int q = 0; q < 4; q++) d[mt][nt][q] = 0.f;

    // A ldmatrix.x4 lane address: m0=(r0-7,k0-7) m1=(r8-15,k0-7) m2=(r0-7,k8-15) m3=(r8-15,k8-15)
    int am = lane >> 3, ar = lane & 7;
    uint32_t aoff = 2u * ((uint32_t)(wrow + (am & 1) * 8 + ar) * STRIDE + (am >> 1) * 8);
    uint32_t aH = smem_u32(sAh) + aoff;
    uint32_t aL = smem_u32(sAl) + aoff;

    // B ldmatrix.x4 lane address: m0=(n0-7,k0-7) m1=(n0-7,k8-15) m2=(n8-15,k0-7) m3=(n8-15,k8-15)
    uint32_t boff = 2u * ((uint32_t)(ncol0 + ((lane >> 4) << 3) + (lane & 7)) * STRIDE
                          + (((lane >> 3) & 1) << 3));
    uint32_t bH = smem_u32(sWh) + boff;
    uint32_t bL = smem_u32(sWl) + boff;

#pragma unroll
    for (int kt = 0; kt < 8; kt++) {
        uint32_t ko = kt * 32;   // 16 bf16 = 32 bytes per k-step
        uint32_t ah0[4], al0[4], ah1[4], al1[4];
        ldsm_x4(ah0, aH + ko);
        ldsm_x4(al0, aL + ko);
        ldsm_x4(ah1, aH + MT_BYTES + ko);     // second m-tile = +16 rows
        ldsm_x4(al1, aL + MT_BYTES + ko);
#pragma unroll
        for (int p = 0; p < 4; p++) {
            uint32_t bh[4], bl[4];
            ldsm_x4(bh, bH + p * MT_BYTES + ko);
            ldsm_x4(bl, bL + p * MT_BYTES + ko);
            mma_bf16(d[0][2 * p],     ah0, bh);     mma_bf16(d[0][2 * p],     ah0, bl);
            mma_bf16(d[0][2 * p],     al0, bh);
            mma_bf16(d[0][2 * p + 1], ah0, bh + 2); mma_bf16(d[0][2 * p + 1], ah0, bl + 2);
            mma_bf16(d[0][2 * p + 1], al0, bh + 2);
            mma_bf16(d[1][2 * p],     ah1, bh);     mma_bf16(d[1][2 * p],     ah1, bl);
            mma_bf16(d[1][2 * p],     al1, bh);
            mma_bf16(d[1][2 * p + 1], ah1, bh + 2); mma_bf16(d[1][2 * p + 1], ah1, bl + 2);
            mma_bf16(d[1][2 * p + 1], al1, bh + 2);
        }
    }

    // epilogue: D fragments -> fp16 g_supp
#pragma unroll
    for (int mt = 0; mt < 2; mt++) {
        int rA = row0 + wrow + mt * 16 + (lane >> 2);
        int rB = rA + 8;
        int cb = 2 * (lane & 3);
#pragma unroll
        for (int nt = 0; nt < 8; nt++) {
            int c = ncol0 + nt * 8 + cb;
            if (rA < N_NODES)
                g_supp[(size_t)rA * 64 + (c >> 1)] = __floats2half2_rn(d[mt][nt][0], d[mt][nt][1]);
            if (rB < N_NODES)
                g_supp[(size_t)rB * 64 + (c >> 1)] = __floats2half2_rn(d[mt][nt][2], d[mt][nt][3]);
        }
    }
}

// ---------------------------------------------------------------------------
// 4) SpMM: one warp per destination row, fp16 gathers, 4-edge unroll (MLP)
// ---------------------------------------------------------------------------
__device__ __forceinline__ void spmm_edge(float4& acc, int2 cv, int lane) {
    float v = __int_as_float(cv.y);
    uint2 p = *(const uint2*)(g_supp + (size_t)cv.x * 64 + lane * 2);
    float2 fa = __half22float2(*(const __half2*)&p.x);
    float2 fb = __half22float2(*(const __half2*)&p.y);
    acc.x = fmaf(v, fa.x, acc.x); acc.y = fmaf(v, fa.y, acc.y);
    acc.z = fmaf(v, fb.x, acc.z); acc.w = fmaf(v, fb.y, acc.w);
}

__global__ void k_spmm(const float* __restrict__ bias,
                       float* __restrict__ out) {
    int gtid = blockIdx.x * blockDim.x + threadIdx.x;
    int row = gtid >> 5;
    int lane = gtid & 31;
    if (row >= N_NODES) return;

    int deg = g_cnt[row];
    if (deg > ELL_CAP) deg = ELL_CAP;
    const int2* rowp = g_ell + (size_t)row * ELL_CAP;

    float4 acc = ((const float4*)bias)[lane];

    int j = 0;
    for (; j + 4 <= deg; j += 4) {
        int2 cv0 = rowp[j];
        int2 cv1 = rowp[j + 1];
        int2 cv2 = rowp[j + 2];
        int2 cv3 = rowp[j + 3];
        spmm_edge(acc, cv0, lane);
        spmm_edge(acc, cv1, lane);
        spmm_edge(acc, cv2, lane);
        spmm_edge(acc, cv3, lane);
    }
    for (; j < deg; j++)
        spmm_edge(acc, rowp[j], lane);

    ((float4*)(out + (size_t)row * F))[lane] = acc;
}

// ---------------------------------------------------------------------------
// launcher: fork GEMM chain onto side stream, overlap with ELL build
// ---------------------------------------------------------------------------
extern "C" void kernel_launch(void* const* d_in, const int* in_sizes, int n_in,
                              void* d_out, int out_size) {
    const float* x        = (const float*)d_in[0];
    const int*   edge_row = (const int*)d_in[1];
    const int*   edge_col = (const int*)d_in[2];
    const float* edge_val = (const float*)d_in[3];
    const float* weight   = (const float*)d_in[4];
    const float* bias     = (const float*)d_in[5];
    float* out = (float*)d_out;

    (void)in_sizes; (void)n_in; (void)out_size;

    static cudaStream_t s2 = nullptr;
    static cudaEvent_t eFork = nullptr, eGemm = nullptr;
    if (s2 == nullptr) {
        cudaStreamCreateWithFlags(&s2, cudaStreamNonBlocking);
        cudaEventCreateWithFlags(&eFork, cudaEventDisableTiming);
        cudaEventCreateWithFlags(&eGemm, cudaEventDisableTiming);
        cudaFuncSetAttribute(k_gemm_mma, cudaFuncAttributeMaxDynamicSharedMemorySize,
                             SMEM_GEMM);
    }

    // fork: GEMM chain on s2
    cudaEventRecord(eFork, 0);
    cudaStreamWaitEvent(s2, eFork, 0);
    k_prep_w<<<128, 128, 0, s2>>>(weight);
    {
        int grid = (N_NODES + 127) / 128;   // 391
        k_gemm_mma<<<grid, 256, SMEM_GEMM, s2>>>(x);
    }
    cudaEventRecord(eGemm, s2);

    // main stream: zero counters, then single-pass ELL scatter
    {
        void* p_cnt = nullptr;
        cudaGetSymbolAddress(&p_cnt, g_cnt);
        cudaMemsetAsync(p_cnt, 0, N_NODES * sizeof(int));
        int blk = 256;
        int nthreads = N_EDGES / 2;
        k_scatter_ell<<<(nthreads + blk - 1) / blk, blk>>>(edge_row, edge_col, edge_val);
    }

    // join, then SpMM
    cudaStreamWaitEvent(0, eGemm, 0);
    {
        int threads = 256;
        long total = (long)N_NODES * 32;
        int grid = (int)((total + threads - 1) / threads);
        k_spmm<<<grid, threads>>>(bias, out);
    }
}

// round 16
// speedup vs baseline: 1.3954x; 1.3954x over previous
#include <cuda_runtime.h>
#include <cuda_bf16.h>
#include <cuda_fp16.h>
#include <cstdint>

#define N_NODES 50000
#define N_EDGES 800000
#define F 128
#define ELL_CAP 64        // P(Poisson(16) >= 64) ~ 4e-18; clamped defensively

// ---------------------------------------------------------------------------
// Device-global scratch (allocation-free rule)
// ---------------------------------------------------------------------------
__device__ __half2 g_supp[(size_t)N_NODES * 64];         // X @ W in fp16; row = 64 half2 = 256 BYTES
__device__ int     g_cnt[N_NODES];                       // per-row edge count
__device__ int2    g_ell[(size_t)N_NODES * ELL_CAP];     // padded bins {col, val bits} (25.6 MB)
__device__ __nv_bfloat16 g_whi[128 * 128];               // W^T hi, row-major [n][k]
__device__ __nv_bfloat16 g_wlo[128 * 128];               // W^T lo

// ---------------------------------------------------------------------------
// helpers
// ---------------------------------------------------------------------------
__device__ __forceinline__ uint32_t smem_u32(const void* p) {
    uint32_t a;
    asm("{ .reg .u64 t; cvta.to.shared.u64 t, %1; cvt.u32.u64 %0, t; }" : "=r"(a) : "l"(p));
    return a;
}
__device__ __forceinline__ void ldsm_x4(uint32_t* r, uint32_t addr) {
    asm volatile("ldmatrix.sync.aligned.m8n8.x4.shared.b16 {%0,%1,%2,%3}, [%4];"
                 : "=r"(r[0]), "=r"(r[1]), "=r"(r[2]), "=r"(r[3]) : "r"(addr));
}
__device__ __forceinline__ void mma_bf16(float* d, const uint32_t* a, const uint32_t* b) {
    asm volatile("mma.sync.aligned.m16n8k16.row.col.f32.bf16.bf16.f32 "
                 "{%0,%1,%2,%3}, {%4,%5,%6,%7}, {%8,%9}, {%0,%1,%2,%3};"
                 : "+f"(d[0]), "+f"(d[1]), "+f"(d[2]), "+f"(d[3])
                 : "r"(a[0]), "r"(a[1]), "r"(a[2]), "r"(a[3]), "r"(b[0]), "r"(b[1]));
}
__device__ __forceinline__ uint32_t packbf(float a, float b) {
    uint32_t r;
    asm("cvt.rn.bf16x2.f32 %0, %1, %2;" : "=r"(r) : "f"(b), "f"(a));
    return r;
}

// ---------------------------------------------------------------------------
// 1) single-pass edge scatter into padded ELL bins
// ---------------------------------------------------------------------------
__global__ void k_scatter_ell(const int* __restrict__ edge_row,
                              const int* __restrict__ edge_col,
                              const float* __restrict__ edge_val) {
    int t = blockIdx.x * blockDim.x + threadIdx.x;
    int e0 = t * 2;
    if (e0 >= N_EDGES) return;

    int2   r2 = ((const int2*)edge_row)[t];
    int2   c2 = ((const int2*)edge_col)[t];
    float2 v2 = ((const float2*)edge_val)[t];

    int pos0 = atomicAdd(&g_cnt[r2.x], 1);
    if (pos0 < ELL_CAP)
        g_ell[(size_t)r2.x * ELL_CAP + pos0] = make_int2(c2.x, __float_as_int(v2.x));
    int pos1 = atomicAdd(&g_cnt[r2.y], 1);
    if (pos1 < ELL_CAP)
        g_ell[(size_t)r2.y * ELL_CAP + pos1] = make_int2(c2.y, __float_as_int(v2.y));
}

// ---------------------------------------------------------------------------
// 2) prep: W[K][N] -> W^T bf16 hi/lo, row-major [n][k]
// ---------------------------------------------------------------------------
__global__ void k_prep_w(const float* __restrict__ weight) {
    int k = blockIdx.x;     // 128 blocks
    int n = threadIdx.x;    // 128 threads, coalesced read
    float v = weight[k * 128 + n];
    __nv_bfloat16 h = __float2bfloat16(v);
    g_whi[n * 128 + k] = h;
    g_wlo[n * 128 + k] = __float2bfloat16(v - __bfloat162float(h));
}

// ---------------------------------------------------------------------------
// 3) GEMM via mma.sync bf16-split: g_supp = fp16(X @ W)  (R10-proven)
// ---------------------------------------------------------------------------
#define STRIDE 136
#define PLANE  (128 * STRIDE)               // bf16 elems per plane
#define MT_BYTES (16 * STRIDE * 2)          // 16 rows, bytes
#define SMEM_GEMM (4 * PLANE * (int)sizeof(__nv_bfloat16))

__global__ void __launch_bounds__(256, 1)
k_gemm_mma(const float* __restrict__ x) {
    extern __shared__ __nv_bfloat16 sm[];
    __nv_bfloat16* sAh = sm;
    __nv_bfloat16* sAl = sm + PLANE;
    __nv_bfloat16* sWh = sm + 2 * PLANE;
    __nv_bfloat16* sWl = sm + 3 * PLANE;

    int tid = threadIdx.x;
    int warp = tid >> 5;
    int lane = tid & 31;
    int row0 = blockIdx.x * 128;

    // stage W planes (row n = 256 B = 16 uint4)
    for (int i = tid; i < 128 * 16; i += 256) {
        int n = i >> 4, q = i & 15;
        ((uint4*)(sWh + n * STRIDE))[q] = ((const uint4*)(g_whi + n * 128))[q];
        ((uint4*)(sWl + n * STRIDE))[q] = ((const uint4*)(g_wlo + n * 128))[q];
    }

    // convert X tile -> bf16 hi/lo. thread t: row = t/2, k-half = t%2
    {
        int row = tid >> 1;
        int kb = (tid & 1) * 64;
        int gr = row0 + row;
        bool valid = (gr < N_NODES);
        const float4* src = (const float4*)(x + (size_t)(valid ? gr : 0) * F + kb);
#pragma unroll
        for (int q = 0; q < 16; q++) {
            float4 v = valid ? src[q] : make_float4(0.f, 0.f, 0.f, 0.f);
            int c = kb + q * 4;
            uint32_t hp0 = packbf(v.x, v.y);
            __nv_bfloat162 h0 = *reinterpret_cast<__nv_bfloat162*>(&hp0);
            uint32_t lp0 = packbf(v.x - __bfloat162float(h0.x), v.y - __bfloat162float(h0.y));
            uint32_t hp1 = packbf(v.z, v.w);
            __nv_bfloat162 h1 = *reinterpret_cast<__nv_bfloat162*>(&hp1);
            uint32_t lp1 = packbf(v.z - __bfloat162float(h1.x), v.w - __bfloat162float(h1.y));
            *(uint32_t*)(sAh + row * STRIDE + c)     = hp0;
            *(uint32_t*)(sAl + row * STRIDE + c)     = lp0;
            *(uint32_t*)(sAh + row * STRIDE + c + 2) = hp1;
            *(uint32_t*)(sAl + row * STRIDE + c + 2) = lp1;
        }
    }
    __syncthreads();

    int warp_m = warp & 3;            // rows warp_m*32
    int warp_n = warp >> 2;           // cols warp_n*64
    int wrow = warp_m * 32;
    int ncol0 = warp_n * 64;

    float d[2][8][4];
#pragma unroll
    for (int mt = 0; mt < 2; mt++)
#pragma unroll
        for (int nt = 0; nt < 8; nt++)
#pragma unroll
            for (int q = 0; q < 4; q++) d[mt][nt][q] = 0.f;

    int am = lane >> 3, ar = lane & 7;
    uint32_t aoff = 2u * ((uint32_t)(wrow + (am & 1) * 8 + ar) * STRIDE + (am >> 1) * 8);
    uint32_t aH = smem_u32(sAh) + aoff;
    uint32_t aL = smem_u32(sAl) + aoff;

    uint32_t boff = 2u * ((uint32_t)(ncol0 + ((lane >> 4) << 3) + (lane & 7)) * STRIDE
                          + (((lane >> 3) & 1) << 3));
    uint32_t bH = smem_u32(sWh) + boff;
    uint32_t bL = smem_u32(sWl) + boff;

#pragma unroll
    for (int kt = 0; kt < 8; kt++) {
        uint32_t ko = kt * 32;   // 16 bf16 = 32 bytes per k-step
        uint32_t ah0[4], al0[4], ah1[4], al1[4];
        ldsm_x4(ah0, aH + ko);
        ldsm_x4(al0, aL + ko);
        ldsm_x4(ah1, aH + MT_BYTES + ko);     // second m-tile = +16 rows
        ldsm_x4(al1, aL + MT_BYTES + ko);
#pragma unroll
        for (int p = 0; p < 4; p++) {
            uint32_t bh[4], bl[4];
            ldsm_x4(bh, bH + p * MT_BYTES + ko);
            ldsm_x4(bl, bL + p * MT_BYTES + ko);
            mma_bf16(d[0][2 * p],     ah0, bh);     mma_bf16(d[0][2 * p],     ah0, bl);
            mma_bf16(d[0][2 * p],     al0, bh);
            mma_bf16(d[0][2 * p + 1], ah0, bh + 2); mma_bf16(d[0][2 * p + 1], ah0, bl + 2);
            mma_bf16(d[0][2 * p + 1], al0, bh + 2);
            mma_bf16(d[1][2 * p],     ah1, bh);     mma_bf16(d[1][2 * p],     ah1, bl);
            mma_bf16(d[1][2 * p],     al1, bh);
            mma_bf16(d[1][2 * p + 1], ah1, bh + 2); mma_bf16(d[1][2 * p + 1], ah1, bl + 2);
            mma_bf16(d[1][2 * p + 1], al1, bh + 2);
        }
    }

    // epilogue: D fragments -> fp16 g_supp
#pragma unroll
    for (int mt = 0; mt < 2; mt++) {
        int rA = row0 + wrow + mt * 16 + (lane >> 2);
        int rB = rA + 8;
        int cb = 2 * (lane & 3);
#pragma unroll
        for (int nt = 0; nt < 8; nt++) {
            int c = ncol0 + nt * 8 + cb;
            if (rA < N_NODES)
                g_supp[(size_t)rA * 64 + (c >> 1)] = __floats2half2_rn(d[mt][nt][0], d[mt][nt][1]);
            if (rB < N_NODES)
                g_supp[(size_t)rB * 64 + (c >> 1)] = __floats2half2_rn(d[mt][nt][2], d[mt][nt][3]);
        }
    }
}

// ---------------------------------------------------------------------------
// 4) SpMM: one warp per row; 8-edge batches, all 8 gathers in flight.
//    Byte addressing: supp row = 256 BYTES (128 fp16), lane covers 8 bytes.
// ---------------------------------------------------------------------------
#define EDGE_FMA(pp, vbits) do {                                           \
    float _v = __int_as_float((int)(vbits));                               \
    float2 _fa = __half22float2(*(const __half2*)&(pp).x);                 \
    float2 _fb = __half22float2(*(const __half2*)&(pp).y);                 \
    acc.x = fmaf(_v, _fa.x, acc.x); acc.y = fmaf(_v, _fa.y, acc.y);        \
    acc.z = fmaf(_v, _fb.x, acc.z); acc.w = fmaf(_v, _fb.y, acc.w);        \
} while (0)

__global__ void k_spmm(const float* __restrict__ bias,
                       float* __restrict__ out) {
    int gtid = blockIdx.x * blockDim.x + threadIdx.x;
    int row = gtid >> 5;
    int lane = gtid & 31;
    if (row >= N_NODES) return;

    int deg = g_cnt[row];
    if (deg > ELL_CAP) deg = ELL_CAP;
    const int2* rowp = g_ell + (size_t)row * ELL_CAP;
    const char* sb = (const char*)g_supp;
    uint32_t loff = (uint32_t)lane * 8u;          // 32 lanes x 8 B = 256 B row

    float4 acc = ((const float4*)bias)[lane];

    int j = 0;
    for (; j + 8 <= deg; j += 8) {
        int2 c0 = rowp[j + 0];
        int2 c1 = rowp[j + 1];
        int2 c2 = rowp[j + 2];
        int2 c3 = rowp[j + 3];
        int2 c4 = rowp[j + 4];
        int2 c5 = rowp[j + 5];
        int2 c6 = rowp[j + 6];
        int2 c7 = rowp[j + 7];
        // 8 independent gathers; row stride = 256 bytes (fp16 support)
        uint2 p0 = *(const uint2*)(sb + (size_t)c0.x * 256 + loff);
        uint2 p1 = *(const uint2*)(sb + (size_t)c1.x * 256 + loff);
        uint2 p2 = *(const uint2*)(sb + (size_t)c2.x * 256 + loff);
        uint2 p3 = *(const uint2*)(sb + (size_t)c3.x * 256 + loff);
        uint2 p4 = *(const uint2*)(sb + (size_t)c4.x * 256 + loff);
        uint2 p5 = *(const uint2*)(sb + (size_t)c5.x * 256 + loff);
        uint2 p6 = *(const uint2*)(sb + (size_t)c6.x * 256 + loff);
        uint2 p7 = *(const uint2*)(sb + (size_t)c7.x * 256 + loff);
        EDGE_FMA(p0, c0.y); EDGE_FMA(p1, c1.y);
        EDGE_FMA(p2, c2.y); EDGE_FMA(p3, c3.y);
        EDGE_FMA(p4, c4.y); EDGE_FMA(p5, c5.y);
        EDGE_FMA(p6, c6.y); EDGE_FMA(p7, c7.y);
    }
    for (; j < deg; j++) {
        int2 cv = rowp[j];
        uint2 p = *(const uint2*)(sb + (size_t)cv.x * 256 + loff);
        EDGE_FMA(p, cv.y);
    }

    ((float4*)(out + (size_t)row * F))[lane] = acc;
}

// ---------------------------------------------------------------------------
// launcher: fork GEMM chain onto side stream, overlap with ELL build
// ---------------------------------------------------------------------------
extern "C" void kernel_launch(void* const* d_in, const int* in_sizes, int n_in,
                              void* d_out, int out_size) {
    const float* x        = (const float*)d_in[0];
    const int*   edge_row = (const int*)d_in[1];
    const int*   edge_col = (const int*)d_in[2];
    const float* edge_val = (const float*)d_in[3];
    const float* weight   = (const float*)d_in[4];
    const float* bias     = (const float*)d_in[5];
    float* out = (float*)d_out;

    (void)in_sizes; (void)n_in; (void)out_size;

    static cudaStream_t s2 = nullptr;
    static cudaEvent_t eFork = nullptr, eGemm = nullptr;
    if (s2 == nullptr) {
        cudaStreamCreateWithFlags(&s2, cudaStreamNonBlocking);
        cudaEventCreateWithFlags(&eFork, cudaEventDisableTiming);
        cudaEventCreateWithFlags(&eGemm, cudaEventDisableTiming);
        cudaFuncSetAttribute(k_gemm_mma, cudaFuncAttributeMaxDynamicSharedMemorySize,
                             SMEM_GEMM);
    }

    // fork: GEMM chain on s2
    cudaEventRecord(eFork, 0);
    cudaStreamWaitEvent(s2, eFork, 0);
    k_prep_w<<<128, 128, 0, s2>>>(weight);
    {
        int grid = (N_NODES + 127) / 128;   // 391
        k_gemm_mma<<<grid, 256, SMEM_GEMM, s2>>>(x);
    }
    cudaEventRecord(eGemm, s2);

    // main stream: zero counters, then single-pass ELL scatter
    {
        void* p_cnt = nullptr;
        cudaGetSymbolAddress(&p_cnt, g_cnt);
        cudaMemsetAsync(p_cnt, 0, N_NODES * sizeof(int));
        int blk = 256;
        int nthreads = N_EDGES / 2;
        k_scatter_ell<<<(nthreads + blk - 1) / blk, blk>>>(edge_row, edge_col, edge_val);
    }

    // join, then SpMM
    cudaStreamWaitEvent(0, eGemm, 0);
    {
        int threads = 256;
        long total = (long)N_NODES * 32;
        int grid = (int)((total + threads - 1) / threads);
        k_spmm<<<grid, threads>>>(bias, out);
    }
}